// round 1
// baseline (speedup 1.0000x reference)
#include <cuda_runtime.h>

// Problem constants (fixed shapes from setup_inputs)
#define B_  4
#define C_  256
#define H_  64
#define W_  64
#define CO_ 256
#define S_  4096        // H*W (== Ho*Wo since stride=1, pad=1, 3x3)
#define KT_ 9

// Scratch (device globals; no allocation allowed)
__device__ __align__(256) float g_xt[B_ * S_ * C_];     // x transposed to [B, HW, C]  (16.78 MB)
__device__ __align__(256) float g_wt[KT_ * C_ * CO_];   // weight transposed to [k][c][co] (2.36 MB)

// ---------------------------------------------------------------------------
// Transpose x: [B, C, HW] -> [B, HW, C]   (32x32 smem tiles)
// ---------------------------------------------------------------------------
__global__ void transpose_x_kernel(const float* __restrict__ x) {
    __shared__ float tile[32][33];
    const int b  = blockIdx.z;
    const int sb = blockIdx.x * 32;  // spatial base
    const int cb = blockIdx.y * 32;  // channel base
    const int tx = threadIdx.x;      // 32
    const int ty = threadIdx.y;      // 8

    const float* xb = x + (size_t)b * C_ * S_;
#pragma unroll
    for (int i = 0; i < 32; i += 8)
        tile[ty + i][tx] = xb[(size_t)(cb + ty + i) * S_ + sb + tx];
    __syncthreads();
    float* xtb = g_xt + (size_t)b * S_ * C_;
#pragma unroll
    for (int i = 0; i < 32; i += 8)
        xtb[(size_t)(sb + ty + i) * C_ + cb + tx] = tile[tx][ty + i];
}

// ---------------------------------------------------------------------------
// Transpose weight: [Co, C, 3, 3] -> [k][c][co]
// ---------------------------------------------------------------------------
__global__ void transpose_w_kernel(const float* __restrict__ w) {
    int idx = blockIdx.x * blockDim.x + threadIdx.x;
    if (idx >= KT_ * C_ * CO_) return;
    int co = idx % CO_;
    int c  = (idx / CO_) % C_;
    int k  = idx / (CO_ * C_);
    g_wt[idx] = w[((size_t)co * C_ + c) * KT_ + k];
}

// ---------------------------------------------------------------------------
// Fused deformable-conv implicit GEMM (fp32 FFMA)
//   M = Co (BM=128), N = positions (BN=128 within one image), K = C*9 (CK=16 per tap)
// ---------------------------------------------------------------------------
#define BM 128
#define BN 128
#define CK 16

struct Meta { float w0, w1, w2, w3; int i0, i1, i2, i3; };

__global__ __launch_bounds__(256) void deform_gemm_kernel(
    const float* __restrict__ offset, float* __restrict__ out)
{
    __shared__ float As[CK][BM];   // weights chunk   (8 KB)
    __shared__ float Bs[CK][BN];   // columns chunk   (8 KB)
    __shared__ Meta  meta[BN];     // bilinear metadata per position (4 KB)

    const int b   = blockIdx.z;
    const int co0 = blockIdx.y * BM;
    const int p0  = blockIdx.x * BN;
    const int tid = threadIdx.x;

    // GEMM micro-tile mapping: 16x16 threads; each thread owns 8x8 outputs
    // split as 2x(4co) x 2x(4p) (columns tx*4 and 64+tx*4) for conflict-free LDS.128
    const int tx = tid & 15;
    const int ty = tid >> 4;

    // Bs-build mapping: 2 threads per position, 8 channels each
    const int pl = tid >> 1;
    const int ch = (tid & 1) * 8;

    float acc[8][8];
#pragma unroll
    for (int i = 0; i < 8; ++i)
#pragma unroll
        for (int j = 0; j < 8; ++j) acc[i][j] = 0.0f;

    const float* xtb  = g_xt + (size_t)b * S_ * C_;
    const float* offb = offset + (size_t)b * (2 * KT_) * S_;

#pragma unroll 1
    for (int k = 0; k < KT_; ++k) {
        // ---- bilinear metadata for this tap (shared across all channels & co) ----
        if (tid < BN) {
            const int p  = p0 + tid;
            const int ho = p >> 6;
            const int wo = p & 63;
            const float sy = offb[(size_t)(2 * k) * S_ + p]     + (float)(ho - 1 + k / 3);
            const float sx = offb[(size_t)(2 * k + 1) * S_ + p] + (float)(wo - 1 + k % 3);
            const float y0f = floorf(sy), x0f = floorf(sx);
            const float dy = sy - y0f,  dx = sx - x0f;
            const int y0 = (int)y0f, x0 = (int)x0f;
            const int y1 = y0 + 1,   x1 = x0 + 1;
            const bool vy0 = (y0 >= 0) && (y0 < H_);
            const bool vy1 = (y1 >= 0) && (y1 < H_);
            const bool vx0 = (x0 >= 0) && (x0 < W_);
            const bool vx1 = (x1 >= 0) && (x1 < W_);
            const int cy0 = min(max(y0, 0), H_ - 1), cy1 = min(max(y1, 0), H_ - 1);
            const int cx0 = min(max(x0, 0), W_ - 1), cx1 = min(max(x1, 0), W_ - 1);
            Meta m;
            m.w0 = (1.0f - dy) * (1.0f - dx) * ((vy0 && vx0) ? 1.0f : 0.0f);
            m.w1 = (1.0f - dy) * dx          * ((vy0 && vx1) ? 1.0f : 0.0f);
            m.w2 = dy * (1.0f - dx)          * ((vy1 && vx0) ? 1.0f : 0.0f);
            m.w3 = dy * dx                   * ((vy1 && vx1) ? 1.0f : 0.0f);
            m.i0 = (cy0 * W_ + cx0) * C_;
            m.i1 = (cy0 * W_ + cx1) * C_;
            m.i2 = (cy1 * W_ + cx0) * C_;
            m.i3 = (cy1 * W_ + cx1) * C_;
            meta[tid] = m;
        }
        __syncthreads();
        const Meta m = meta[pl];

        const float* wk = g_wt + (size_t)k * C_ * CO_ + co0;

#pragma unroll 1
        for (int ct = 0; ct < C_ / CK; ++ct) {
            const int cbase = ct * CK;

            // ---- global loads (before sync, to overlap with previous FFMA) ----
            // A: wt[k][cbase + (tid>>4)][co0 + (tid&15)*8 .. +7]  (coalesced)
            const float4* asrc = (const float4*)(wk + (size_t)(cbase + (tid >> 4)) * CO_ + (tid & 15) * 8);
            const float4 wv0 = asrc[0];
            const float4 wv1 = asrc[1];

            // B: bilinear columns for 8 channels of one position
            const float* base = xtb + cbase + ch;
            const float4 v0a = *(const float4*)(base + m.i0);
            const float4 v0b = *(const float4*)(base + m.i0 + 4);
            const float4 v1a = *(const float4*)(base + m.i1);
            const float4 v1b = *(const float4*)(base + m.i1 + 4);
            const float4 v2a = *(const float4*)(base + m.i2);
            const float4 v2b = *(const float4*)(base + m.i2 + 4);
            const float4 v3a = *(const float4*)(base + m.i3);
            const float4 v3b = *(const float4*)(base + m.i3 + 4);

            float cv[8];
            cv[0] = m.w0 * v0a.x + m.w1 * v1a.x + m.w2 * v2a.x + m.w3 * v3a.x;
            cv[1] = m.w0 * v0a.y + m.w1 * v1a.y + m.w2 * v2a.y + m.w3 * v3a.y;
            cv[2] = m.w0 * v0a.z + m.w1 * v1a.z + m.w2 * v2a.z + m.w3 * v3a.z;
            cv[3] = m.w0 * v0a.w + m.w1 * v1a.w + m.w2 * v2a.w + m.w3 * v3a.w;
            cv[4] = m.w0 * v0b.x + m.w1 * v1b.x + m.w2 * v2b.x + m.w3 * v3b.x;
            cv[5] = m.w0 * v0b.y + m.w1 * v1b.y + m.w2 * v2b.y + m.w3 * v3b.y;
            cv[6] = m.w0 * v0b.z + m.w1 * v1b.z + m.w2 * v2b.z + m.w3 * v3b.z;
            cv[7] = m.w0 * v0b.w + m.w1 * v1b.w + m.w2 * v2b.w + m.w3 * v3b.w;

            __syncthreads();   // previous chunk's FFMA reads done

            // ---- smem stores ----
            float* adst = &As[tid >> 4][(tid & 15) * 8];
            ((float4*)adst)[0] = wv0;
            ((float4*)adst)[1] = wv1;
#pragma unroll
            for (int j = 0; j < 8; ++j) Bs[ch + j][pl] = cv[j];

            __syncthreads();

            // ---- FFMA micro-kernel ----
#pragma unroll
            for (int cc = 0; cc < CK; ++cc) {
                float a[8], bb[8];
                *(float4*)(a)      = *(const float4*)&As[cc][ty * 4];
                *(float4*)(a + 4)  = *(const float4*)&As[cc][64 + ty * 4];
                *(float4*)(bb)     = *(const float4*)&Bs[cc][tx * 4];
                *(float4*)(bb + 4) = *(const float4*)&Bs[cc][64 + tx * 4];
#pragma unroll
                for (int i = 0; i < 8; ++i)
#pragma unroll
                    for (int j = 0; j < 8; ++j)
                        acc[i][j] += a[i] * bb[j];
            }
        }
        __syncthreads();  // meta[] will be rewritten next tap
    }

    // ---- epilogue: out[b][co][p] ----
    float* ob = out + ((size_t)b * CO_ + co0) * S_ + p0;
#pragma unroll
    for (int i = 0; i < 8; ++i) {
        const int co_i = ((i < 4) ? (ty * 4 + i) : (64 + ty * 4 + (i - 4)));
        float4 r0 = make_float4(acc[i][0], acc[i][1], acc[i][2], acc[i][3]);
        float4 r1 = make_float4(acc[i][4], acc[i][5], acc[i][6], acc[i][7]);
        *(float4*)(ob + (size_t)co_i * S_ + tx * 4)      = r0;
        *(float4*)(ob + (size_t)co_i * S_ + 64 + tx * 4) = r1;
    }
}

// ---------------------------------------------------------------------------
// Launch
// ---------------------------------------------------------------------------
extern "C" void kernel_launch(void* const* d_in, const int* in_sizes, int n_in,
                              void* d_out, int out_size)
{
    (void)in_sizes; (void)n_in; (void)out_size;
    const float* x      = (const float*)d_in[0];
    const float* offset = (const float*)d_in[1];
    const float* weight = (const float*)d_in[2];
    float* out          = (float*)d_out;

    {
        dim3 grid(S_ / 32, C_ / 32, B_);
        dim3 block(32, 8);
        transpose_x_kernel<<<grid, block>>>(x);
    }
    {
        int n = KT_ * C_ * CO_;
        transpose_w_kernel<<<(n + 255) / 256, 256>>>(weight);
    }
    {
        dim3 grid(S_ / BN, CO_ / BM, B_);
        deform_gemm_kernel<<<grid, 256>>>(offset, out);
    }
}

// round 3
// speedup vs baseline: 3.0083x; 3.0083x over previous
#include <cuda_runtime.h>
#include <cstdint>

// Problem constants (fixed shapes from setup_inputs)
#define B_  4
#define C_  256
#define H_  64
#define W_  64
#define CO_ 256
#define S_  4096        // H*W (== Ho*Wo since stride=1, pad=1, 3x3)
#define KT_ 9

// GEMM tiling
#define BM 256          // all of Co in one CTA (gather built once per position tile)
#define BN 128
#define CK 16
#define NTHREADS 512
#define ASTR 20         // 16 k-floats + 4 pad (bank-conflict-free frag loads)
#define BSTR 20

// Scratch (device globals; no allocation allowed)
__device__ __align__(256) float g_xt[B_ * S_ * C_];        // x transposed to [B, HW, C]
__device__ __align__(256) float g_wt[KT_ * 16 * CO_ * 16]; // weights [k][ct][co][cc]

// ---------------------------------------------------------------------------
// Transpose x: [B, C, HW] -> [B, HW, C]
// ---------------------------------------------------------------------------
__global__ void transpose_x_kernel(const float* __restrict__ x) {
    __shared__ float tile[32][33];
    const int b  = blockIdx.z;
    const int sb = blockIdx.x * 32;
    const int cb = blockIdx.y * 32;
    const int tx = threadIdx.x;
    const int ty = threadIdx.y;

    const float* xb = x + (size_t)b * C_ * S_;
#pragma unroll
    for (int i = 0; i < 32; i += 8)
        tile[ty + i][tx] = xb[(size_t)(cb + ty + i) * S_ + sb + tx];
    __syncthreads();
    float* xtb = g_xt + (size_t)b * S_ * C_;
#pragma unroll
    for (int i = 0; i < 32; i += 8)
        xtb[(size_t)(sb + ty + i) * C_ + cb + tx] = tile[tx][ty + i];
}

// ---------------------------------------------------------------------------
// Transpose weight: [Co, C, 3, 3] -> [k][ct][co][cc]  (chunk-blocked, c-minor)
// ---------------------------------------------------------------------------
__global__ void transpose_w_kernel(const float* __restrict__ w) {
    int idx = blockIdx.x * blockDim.x + threadIdx.x;
    if (idx >= KT_ * C_ * CO_) return;
    int cc = idx & 15;
    int co = (idx >> 4) & 255;
    int ct = (idx >> 12) & 15;
    int k  = idx >> 16;
    g_wt[idx] = w[((size_t)co * C_ + ct * 16 + cc) * KT_ + k];
}

// ---------------------------------------------------------------------------
// Fused deformable-conv implicit GEMM, tf32 tensor cores (mma.m16n8k8)
// ---------------------------------------------------------------------------
struct Meta { float w0, w1, w2, w3; int i0, i1, i2, i3; };

__device__ __forceinline__ uint32_t to_tf32(float x) {
    uint32_t r;
    asm("cvt.rna.tf32.f32 %0, %1;" : "=r"(r) : "f"(x));
    return r;
}

__device__ __forceinline__ void mma_tf32(float d[4], const uint32_t a[4],
                                         uint32_t b0, uint32_t b1) {
    asm volatile(
        "mma.sync.aligned.m16n8k8.row.col.f32.tf32.tf32.f32 "
        "{%0,%1,%2,%3}, {%4,%5,%6,%7}, {%8,%9}, {%0,%1,%2,%3};"
        : "+f"(d[0]), "+f"(d[1]), "+f"(d[2]), "+f"(d[3])
        : "r"(a[0]), "r"(a[1]), "r"(a[2]), "r"(a[3]), "r"(b0), "r"(b1));
}

__global__ __launch_bounds__(NTHREADS, 1) void deform_gemm_tf32(
    const float* __restrict__ offset, float* __restrict__ out)
{
    __shared__ uint32_t As[BM * ASTR];   // 20 KB: weights chunk [co][16k] (tf32 bits)
    __shared__ uint32_t Bs[BN * BSTR];   // 10 KB: columns chunk [pos][16k] (tf32 bits)
    __shared__ Meta     meta[BN];        //  4 KB

    const int b   = blockIdx.z;
    const int p0  = blockIdx.x * BN;
    const int tid = threadIdx.x;
    const int lane = tid & 31;
    const int warp = tid >> 5;
    const int g   = lane >> 2;        // group id (0..7)
    const int tig = lane & 3;         // thread in group
    const int wm  = (warp >> 2) * 64; // warp m origin (4 warp-rows)
    const int wn  = (warp & 3) * 32;  // warp n origin (4 warp-cols)

    // B-build mapping: 4 threads per position, 4 channels each
    const int pl = tid >> 2;
    const int ch = (tid & 3) * 4;
    // A-build mapping: each thread stores 8 cc of one co (2 threads per co)
    const int aco = tid >> 1;
    const int accb = (tid & 1) * 8;

    float acc[4][4][4];
#pragma unroll
    for (int i = 0; i < 4; ++i)
#pragma unroll
        for (int j = 0; j < 4; ++j)
#pragma unroll
            for (int r = 0; r < 4; ++r) acc[i][j][r] = 0.0f;

    const float* xtb  = g_xt + (size_t)b * S_ * C_;
    const float* offb = offset + (size_t)b * (2 * KT_) * S_;

    float4 cb0, cb1, cb2, cb3;   // prefetched bilinear corners (16 floats)
    float4 wv0, wv1;             // prefetched weights (8 floats)
    Meta m;

#pragma unroll 1
    for (int k = 0; k < KT_; ++k) {
        // ---- bilinear metadata for this tap ----
        if (tid < BN) {
            const int p  = p0 + tid;
            const int ho = p >> 6;
            const int wo = p & 63;
            const float sy = offb[(size_t)(2 * k) * S_ + p]     + (float)(ho - 1 + k / 3);
            const float sx = offb[(size_t)(2 * k + 1) * S_ + p] + (float)(wo - 1 + k % 3);
            const float y0f = floorf(sy), x0f = floorf(sx);
            const float dy = sy - y0f,  dx = sx - x0f;
            const int y0 = (int)y0f, x0 = (int)x0f;
            const int y1 = y0 + 1,   x1 = x0 + 1;
            const bool vy0 = (y0 >= 0) && (y0 < H_);
            const bool vy1 = (y1 >= 0) && (y1 < H_);
            const bool vx0 = (x0 >= 0) && (x0 < W_);
            const bool vx1 = (x1 >= 0) && (x1 < W_);
            const int cy0 = min(max(y0, 0), H_ - 1), cy1 = min(max(y1, 0), H_ - 1);
            const int cx0 = min(max(x0, 0), W_ - 1), cx1 = min(max(x1, 0), W_ - 1);
            Meta mm;
            mm.w0 = (1.0f - dy) * (1.0f - dx) * ((vy0 && vx0) ? 1.0f : 0.0f);
            mm.w1 = (1.0f - dy) * dx          * ((vy0 && vx1) ? 1.0f : 0.0f);
            mm.w2 = dy * (1.0f - dx)          * ((vy1 && vx0) ? 1.0f : 0.0f);
            mm.w3 = dy * dx                   * ((vy1 && vx1) ? 1.0f : 0.0f);
            mm.i0 = (cy0 * W_ + cx0) * C_;
            mm.i1 = (cy0 * W_ + cx1) * C_;
            mm.i2 = (cy1 * W_ + cx0) * C_;
            mm.i3 = (cy1 * W_ + cx1) * C_;
            meta[tid] = mm;
        }
        __syncthreads();
        m = meta[pl];

        // prefetch chunk ct=0
        {
            const float* wsrc = g_wt + ((size_t)k * 16 + 0) * (CO_ * 16) + tid * 8;
            wv0 = ((const float4*)wsrc)[0];
            wv1 = ((const float4*)wsrc)[1];
            const float* base = xtb + ch;
            cb0 = *(const float4*)(base + m.i0);
            cb1 = *(const float4*)(base + m.i1);
            cb2 = *(const float4*)(base + m.i2);
            cb3 = *(const float4*)(base + m.i3);
        }

#pragma unroll 1
        for (int ct = 0; ct < C_ / CK; ++ct) {
            __syncthreads();   // previous chunk's mma reads done

            // ---- store A (weights, tf32-rounded) ----
            {
                uint4 a0 = make_uint4(to_tf32(wv0.x), to_tf32(wv0.y), to_tf32(wv0.z), to_tf32(wv0.w));
                uint4 a1 = make_uint4(to_tf32(wv1.x), to_tf32(wv1.y), to_tf32(wv1.z), to_tf32(wv1.w));
                *(uint4*)&As[aco * ASTR + accb]     = a0;
                *(uint4*)&As[aco * ASTR + accb + 4] = a1;
            }

            // ---- combine corners -> column, store B ----
            {
                uint4 cv;
                cv.x = to_tf32(m.w0 * cb0.x + m.w1 * cb1.x + m.w2 * cb2.x + m.w3 * cb3.x);
                cv.y = to_tf32(m.w0 * cb0.y + m.w1 * cb1.y + m.w2 * cb2.y + m.w3 * cb3.y);
                cv.z = to_tf32(m.w0 * cb0.z + m.w1 * cb1.z + m.w2 * cb2.z + m.w3 * cb3.z);
                cv.w = to_tf32(m.w0 * cb0.w + m.w1 * cb1.w + m.w2 * cb2.w + m.w3 * cb3.w);
                *(uint4*)&Bs[pl * BSTR + ch] = cv;
            }

            __syncthreads();

            // ---- prefetch next chunk (overlaps with mma below) ----
            if (ct < C_ / CK - 1) {
                const float* wsrc = g_wt + ((size_t)k * 16 + ct + 1) * (CO_ * 16) + tid * 8;
                wv0 = ((const float4*)wsrc)[0];
                wv1 = ((const float4*)wsrc)[1];
                const float* base = xtb + (ct + 1) * CK + ch;
                cb0 = *(const float4*)(base + m.i0);
                cb1 = *(const float4*)(base + m.i1);
                cb2 = *(const float4*)(base + m.i2);
                cb3 = *(const float4*)(base + m.i3);
            }

            // ---- tensor-core micro-kernel: warp tile 64m x 32n x 16k ----
#pragma unroll
            for (int ks = 0; ks < 2; ++ks) {
                const int k0 = ks * 8;
                uint32_t a[4][4];
#pragma unroll
                for (int mt = 0; mt < 4; ++mt) {
                    const int mr = wm + mt * 16;
                    a[mt][0] = As[(mr + g) * ASTR + k0 + tig];
                    a[mt][1] = As[(mr + g + 8) * ASTR + k0 + tig];
                    a[mt][2] = As[(mr + g) * ASTR + k0 + tig + 4];
                    a[mt][3] = As[(mr + g + 8) * ASTR + k0 + tig + 4];
                }
#pragma unroll
                for (int nt = 0; nt < 4; ++nt) {
                    const int nr = wn + nt * 8;
                    const uint32_t b0 = Bs[(nr + g) * BSTR + k0 + tig];
                    const uint32_t b1 = Bs[(nr + g) * BSTR + k0 + tig + 4];
#pragma unroll
                    for (int mt = 0; mt < 4; ++mt)
                        mma_tf32(acc[mt][nt], a[mt], b0, b1);
                }
            }
        }
        __syncthreads();  // protect meta[]/As/Bs rewrite vs last mma
    }

    // ---- epilogue: out[b][co][p] ----
    float* ob = out + (size_t)b * CO_ * S_;
#pragma unroll
    for (int mt = 0; mt < 4; ++mt) {
#pragma unroll
        for (int nt = 0; nt < 4; ++nt) {
            const int crow = wm + mt * 16 + g;
            const int pcol = p0 + wn + nt * 8 + 2 * tig;
            *(float2*)&ob[(size_t)crow * S_ + pcol] =
                make_float2(acc[mt][nt][0], acc[mt][nt][1]);
            *(float2*)&ob[(size_t)(crow + 8) * S_ + pcol] =
                make_float2(acc[mt][nt][2], acc[mt][nt][3]);
        }
    }
}

// ---------------------------------------------------------------------------
// Launch
// ---------------------------------------------------------------------------
extern "C" void kernel_launch(void* const* d_in, const int* in_sizes, int n_in,
                              void* d_out, int out_size)
{
    (void)in_sizes; (void)n_in; (void)out_size;
    const float* x      = (const float*)d_in[0];
    const float* offset = (const float*)d_in[1];
    const float* weight = (const float*)d_in[2];
    float* out          = (float*)d_out;

    {
        dim3 grid(S_ / 32, C_ / 32, B_);
        dim3 block(32, 8);
        transpose_x_kernel<<<grid, block>>>(x);
    }
    {
        int n = KT_ * C_ * CO_;
        transpose_w_kernel<<<(n + 255) / 256, 256>>>(weight);
    }
    {
        dim3 grid(S_ / BN, 1, B_);
        deform_gemm_tf32<<<grid, NTHREADS>>>(offset, out);
    }
}

// round 5
// speedup vs baseline: 4.8491x; 1.6119x over previous
#include <cuda_runtime.h>
#include <cuda_fp16.h>
#include <cstdint>

// Problem constants
#define B_  4
#define C_  256
#define H_  64
#define W_  64
#define CO_ 256
#define S_  4096
#define KT_ 9

#define BN  128          // positions per CTA
#define CKC 32           // channels per K-chunk
#define NCH 72           // chunks = 9 taps * 8
#define NTH 512
#define ASTRH 40         // A row stride in halves (32 + 8 pad)
#define BSTRH 40

// Dynamic smem map (bytes)
#define SM_A    0        // 2 stages x 256*40*2  = 40960
#define SM_B    40960    // 2 stages x 128*40*2  = 20480
#define SM_META 61440    // Meta[128]            = 4096
#define SMEM_SZ 65536
#define ASTAGE  20480
#define BSTAGE  10240

// Scratch
__device__ __align__(256) float g_xt[B_ * S_ * C_];              // x -> [B, HW, C]
__device__ __align__(256) half  g_wAh[NCH * CO_ * ASTRH];        // prepped fp16 A images

struct Meta { float w0, w1, w2, w3; int i0, i1, i2, i3; };

// ---------------------------------------------------------------------------
// Helpers
// ---------------------------------------------------------------------------
__device__ __forceinline__ uint32_t smem_u32(const void* p) {
    uint32_t a;
    asm("{ .reg .u64 t; cvta.to.shared.u64 t, %1; cvt.u32.u64 %0, t; }" : "=r"(a) : "l"(p));
    return a;
}
__device__ __forceinline__ void ldsm_x4(uint32_t& r0, uint32_t& r1, uint32_t& r2, uint32_t& r3,
                                        uint32_t addr) {
    asm volatile("ldmatrix.sync.aligned.m8n8.x4.shared.b16 {%0,%1,%2,%3}, [%4];"
                 : "=r"(r0), "=r"(r1), "=r"(r2), "=r"(r3) : "r"(addr));
}
__device__ __forceinline__ void mma_fp16(float d[4], uint32_t a0, uint32_t a1,
                                         uint32_t a2, uint32_t a3,
                                         uint32_t b0, uint32_t b1) {
    asm volatile(
        "mma.sync.aligned.m16n8k16.row.col.f32.f16.f16.f32 "
        "{%0,%1,%2,%3}, {%4,%5,%6,%7}, {%8,%9}, {%0,%1,%2,%3};"
        : "+f"(d[0]), "+f"(d[1]), "+f"(d[2]), "+f"(d[3])
        : "r"(a0), "r"(a1), "r"(a2), "r"(a3), "r"(b0), "r"(b1));
}
#define CP_ASYNC16(dst, src) \
    asm volatile("cp.async.ca.shared.global [%0], [%1], 16;" :: "r"(dst), "l"(src))
#define CP_COMMIT() asm volatile("cp.async.commit_group;" ::: "memory")
#define CP_WAIT0()  asm volatile("cp.async.wait_group 0;" ::: "memory")

// ---------------------------------------------------------------------------
// Transpose x: [B, C, HW] -> [B, HW, C]
// ---------------------------------------------------------------------------
__global__ void transpose_x_kernel(const float* __restrict__ x) {
    __shared__ float tile[32][33];
    const int b  = blockIdx.z;
    const int sb = blockIdx.x * 32;
    const int cb = blockIdx.y * 32;
    const int tx = threadIdx.x;
    const int ty = threadIdx.y;
    const float* xb = x + (size_t)b * C_ * S_;
#pragma unroll
    for (int i = 0; i < 32; i += 8)
        tile[ty + i][tx] = xb[(size_t)(cb + ty + i) * S_ + sb + tx];
    __syncthreads();
    float* xtb = g_xt + (size_t)b * S_ * C_;
#pragma unroll
    for (int i = 0; i < 32; i += 8)
        xtb[(size_t)(sb + ty + i) * C_ + cb + tx] = tile[tx][ty + i];
}

// ---------------------------------------------------------------------------
// Prep weights: fp16 A images [q][co][40] (row = co, 32 channels + 8 pad)
// ---------------------------------------------------------------------------
__global__ void prep_w_kernel(const float* __restrict__ w) {
    int idx = blockIdx.x * blockDim.x + threadIdx.x;
    if (idx >= NCH * CO_ * ASTRH) return;
    int cc = idx % ASTRH;
    int co = (idx / ASTRH) & 255;
    int q  = idx / (ASTRH * CO_);
    int k  = q >> 3;
    int c  = (q & 7) * 32 + cc;
    half v = __float2half(0.0f);
    if (cc < 32) v = __float2half(w[((size_t)co * C_ + c) * KT_ + k]);
    g_wAh[idx] = v;
}

// ---------------------------------------------------------------------------
// Main: fp16 mma.sync implicit GEMM with bilinear-gathered B
// ---------------------------------------------------------------------------
__global__ __launch_bounds__(NTH, 1) void deform_fp16_kernel(
    const float* __restrict__ offset, float* __restrict__ out)
{
    extern __shared__ __align__(1024) char smem[];
    const uint32_t sbase = smem_u32(smem);
    Meta* metap = (Meta*)(smem + SM_META);

    const int tid  = threadIdx.x;
    const int lane = tid & 31;
    const int warp = tid >> 5;
    const int b    = blockIdx.y;
    const int p0   = blockIdx.x * BN;

    const int g   = lane >> 2;
    const int tig = lane & 3;
    const int wm  = (warp >> 2) * 64;   // warp m origin
    const int wn  = (warp & 3) * 32;    // warp n origin

    // B build mapping: 4 threads per position, 8 channels each
    const int pl  = tid >> 2;
    const int ch0 = (tid & 3) * 8;

    const float* xtb  = g_xt + (size_t)b * S_ * C_;
    const float* offb = offset + (size_t)b * (2 * KT_) * S_;

    float acc[4][4][4];
#pragma unroll
    for (int i = 0; i < 4; ++i)
#pragma unroll
        for (int j = 0; j < 4; ++j)
#pragma unroll
            for (int r = 0; r < 4; ++r) acc[i][j][r] = 0.0f;

    // ldmatrix lane address components (bytes within a stage)
    const uint32_t aRowOff = (uint32_t)(wm + (lane & 7) + ((lane >> 3) & 1) * 8) * (ASTRH * 2)
                           + (lane >> 4) * 16;                 // + mt*16 rows + ks*32B
    const uint32_t bRowOff = (uint32_t)(wn + (lane & 7)) * (BSTRH * 2)
                           + (lane >> 3) * 16;                 // + nt*8 rows

    auto write_meta = [&](int k) {
        if (tid < BN) {
            const int p  = p0 + tid;
            const int ho = p >> 6;
            const int wo = p & 63;
            const float sy = offb[(size_t)(2 * k) * S_ + p]     + (float)(ho - 1 + k / 3);
            const float sx = offb[(size_t)(2 * k + 1) * S_ + p] + (float)(wo - 1 + k % 3);
            const float y0f = floorf(sy), x0f = floorf(sx);
            const float dy = sy - y0f,  dx = sx - x0f;
            const int y0 = (int)y0f, x0 = (int)x0f;
            const int y1 = y0 + 1,   x1 = x0 + 1;
            const bool vy0 = (y0 >= 0) && (y0 < H_);
            const bool vy1 = (y1 >= 0) && (y1 < H_);
            const bool vx0 = (x0 >= 0) && (x0 < W_);
            const bool vx1 = (x1 >= 0) && (x1 < W_);
            const int cy0 = min(max(y0, 0), H_ - 1), cy1 = min(max(y1, 0), H_ - 1);
            const int cx0 = min(max(x0, 0), W_ - 1), cx1 = min(max(x1, 0), W_ - 1);
            Meta mm;
            mm.w0 = (1.0f - dy) * (1.0f - dx) * ((vy0 && vx0) ? 1.0f : 0.0f);
            mm.w1 = (1.0f - dy) * dx          * ((vy0 && vx1) ? 1.0f : 0.0f);
            mm.w2 = dy * (1.0f - dx)          * ((vy1 && vx0) ? 1.0f : 0.0f);
            mm.w3 = dy * dx                   * ((vy1 && vx1) ? 1.0f : 0.0f);
            mm.i0 = (cy0 * W_ + cx0) * C_;
            mm.i1 = (cy0 * W_ + cx1) * C_;
            mm.i2 = (cy1 * W_ + cx0) * C_;
            mm.i3 = (cy1 * W_ + cx1) * C_;
            metap[tid] = mm;
        }
    };

    // loads for chunk q: cp.async A image + gather/combine B columns -> cv
    uint32_t cv[4];
    auto do_loads = [&](int q) {
        const int s  = q & 1;
        // A: 1280 uint4 linear copy via cp.async
        const char* asrc = (const char*)g_wAh + (size_t)q * ASTAGE;
        const uint32_t adst = sbase + SM_A + s * ASTAGE;
#pragma unroll
        for (int i = 0; i < 3; ++i) {
            int idx = i * NTH + tid;
            if (idx < ASTAGE / 16)
                CP_ASYNC16(adst + idx * 16, asrc + idx * 16);
        }
        CP_COMMIT();
        // B gathers
        const Meta m = metap[pl];
        const int c0 = (q >> 3 == q >> 3 ? (q & 7) * 32 : 0); // (q&7)*32
        const float* ba = xtb + (q & 7) * 32 + ch0;
        (void)c0;
        const float4 a0 = *(const float4*)(ba + m.i0);
        const float4 a1 = *(const float4*)(ba + m.i1);
        const float4 a2 = *(const float4*)(ba + m.i2);
        const float4 a3 = *(const float4*)(ba + m.i3);
        const float4 b0 = *(const float4*)(ba + 4 + m.i0);
        const float4 b1 = *(const float4*)(ba + 4 + m.i1);
        const float4 b2 = *(const float4*)(ba + 4 + m.i2);
        const float4 b3 = *(const float4*)(ba + 4 + m.i3);
        float f[8];
        f[0] = m.w0 * a0.x + m.w1 * a1.x + m.w2 * a2.x + m.w3 * a3.x;
        f[1] = m.w0 * a0.y + m.w1 * a1.y + m.w2 * a2.y + m.w3 * a3.y;
        f[2] = m.w0 * a0.z + m.w1 * a1.z + m.w2 * a2.z + m.w3 * a3.z;
        f[3] = m.w0 * a0.w + m.w1 * a1.w + m.w2 * a2.w + m.w3 * a3.w;
        f[4] = m.w0 * b0.x + m.w1 * b1.x + m.w2 * b2.x + m.w3 * b3.x;
        f[5] = m.w0 * b0.y + m.w1 * b1.y + m.w2 * b2.y + m.w3 * b3.y;
        f[6] = m.w0 * b0.z + m.w1 * b1.z + m.w2 * b2.z + m.w3 * b3.z;
        f[7] = m.w0 * b0.w + m.w1 * b1.w + m.w2 * b2.w + m.w3 * b3.w;
#pragma unroll
        for (int j = 0; j < 4; ++j) {
            half2 h = __floats2half2_rn(f[2 * j], f[2 * j + 1]);
            cv[j] = *(uint32_t*)&h;
        }
    };

    // ---- prologue ----
    write_meta(0);
    __syncthreads();
    do_loads(0);

#pragma unroll 1
    for (int q = 0; q < NCH; ++q) {
        const int s = q & 1;

        // ---- store B columns for chunk q ----
        {
            uint32_t baddr = sbase + SM_B + s * BSTAGE + (uint32_t)pl * (BSTRH * 2) + ch0 * 2;
            *(uint4*)(smem + (baddr - sbase)) = make_uint4(cv[0], cv[1], cv[2], cv[3]);
        }
        CP_WAIT0();          // A image for chunk q complete
        __syncthreads();

        // ---- meta for next tap, if boundary ----
        if (((q + 1) & 7) == 0 && q + 1 < NCH) {
            write_meta((q + 1) >> 3);
            __syncthreads();
        }

        // ---- issue loads for q+1 (overlaps mma below) ----
        if (q + 1 < NCH) do_loads(q + 1);

        // ---- mma on stage s ----
        const uint32_t aBase = sbase + SM_A + s * ASTAGE + aRowOff;
        const uint32_t bBase = sbase + SM_B + s * BSTAGE + bRowOff;

        uint32_t bf[4][4];
#pragma unroll
        for (int nt = 0; nt < 4; ++nt)
            ldsm_x4(bf[nt][0], bf[nt][1], bf[nt][2], bf[nt][3],
                    bBase + (uint32_t)nt * 8 * (BSTRH * 2));

#pragma unroll
        for (int ks = 0; ks < 2; ++ks) {
#pragma unroll
            for (int mt = 0; mt < 4; ++mt) {
                uint32_t a0, a1, a2, a3;
                ldsm_x4(a0, a1, a2, a3,
                        aBase + (uint32_t)mt * 16 * (ASTRH * 2) + ks * 32);
#pragma unroll
                for (int nt = 0; nt < 4; ++nt)
                    mma_fp16(acc[mt][nt], a0, a1, a2, a3,
                             bf[nt][2 * ks], bf[nt][2 * ks + 1]);
            }
        }
    }

    // ---- epilogue: out[b][co][p] ----
    float* ob = out + (size_t)b * CO_ * S_;
#pragma unroll
    for (int mt = 0; mt < 4; ++mt) {
#pragma unroll
        for (int nt = 0; nt < 4; ++nt) {
            const int crow = wm + mt * 16 + g;
            const int pcol = p0 + wn + nt * 8 + 2 * tig;
            *(float2*)&ob[(size_t)crow * S_ + pcol] =
                make_float2(acc[mt][nt][0], acc[mt][nt][1]);
            *(float2*)&ob[(size_t)(crow + 8) * S_ + pcol] =
                make_float2(acc[mt][nt][2], acc[mt][nt][3]);
        }
    }
}

// ---------------------------------------------------------------------------
// Launch
// ---------------------------------------------------------------------------
extern "C" void kernel_launch(void* const* d_in, const int* in_sizes, int n_in,
                              void* d_out, int out_size)
{
    (void)in_sizes; (void)n_in; (void)out_size;
    const float* x      = (const float*)d_in[0];
    const float* offset = (const float*)d_in[1];
    const float* weight = (const float*)d_in[2];
    float* out          = (float*)d_out;

    static int attr_set = 0;
    if (!attr_set) {
        cudaFuncSetAttribute(deform_fp16_kernel,
                             cudaFuncAttributeMaxDynamicSharedMemorySize, SMEM_SZ);
        attr_set = 1;
    }

    {
        dim3 grid(S_ / 32, C_ / 32, B_);
        dim3 block(32, 8);
        transpose_x_kernel<<<grid, block>>>(x);
    }
    {
        int n = NCH * CO_ * ASTRH;
        prep_w_kernel<<<(n + 255) / 256, 256>>>(weight);
    }
    {
        dim3 grid(S_ / BN, B_);
        deform_fp16_kernel<<<grid, NTH, SMEM_SZ>>>(offset, out);
    }
}

// round 6
// speedup vs baseline: 5.6372x; 1.1625x over previous
#include <cuda_runtime.h>
#include <cuda_fp16.h>
#include <cstdint>

// Problem constants
#define B_  4
#define C_  256
#define H_  64
#define W_  64
#define CO_ 256
#define S_  4096
#define KT_ 9

#define BN  128          // positions per CTA
#define NCH 72           // chunks = 9 taps * 8 (32 channels each)
#define NTH 512
#define ASTRH 40         // A row stride in halves (32 + 8 pad)
#define BSTRH 40

// Dynamic smem map (bytes)
#define SM_A    0        // 2 stages x 256*40*2  = 40960
#define SM_B    40960    // 2 stages x 128*40*2  = 20480
#define SM_META 61440    // Meta[128]            = 4096
#define SMEM_SZ 65536
#define ASTAGE  20480
#define BSTAGE  10240

// Scratch
__device__ __align__(256) half g_xth[B_ * S_ * C_];        // x -> [B, HW, C] fp16 (8 MB)
__device__ __align__(256) half g_wAh[NCH * CO_ * ASTRH];   // prepped fp16 A images

struct Meta { float w0, w1, w2, w3; int i0, i1, i2, i3; };

// ---------------------------------------------------------------------------
// Helpers
// ---------------------------------------------------------------------------
__device__ __forceinline__ uint32_t smem_u32(const void* p) {
    uint32_t a;
    asm("{ .reg .u64 t; cvta.to.shared.u64 t, %1; cvt.u32.u64 %0, t; }" : "=r"(a) : "l"(p));
    return a;
}
__device__ __forceinline__ void ldsm_x4(uint32_t& r0, uint32_t& r1, uint32_t& r2, uint32_t& r3,
                                        uint32_t addr) {
    asm volatile("ldmatrix.sync.aligned.m8n8.x4.shared.b16 {%0,%1,%2,%3}, [%4];"
                 : "=r"(r0), "=r"(r1), "=r"(r2), "=r"(r3) : "r"(addr));
}
__device__ __forceinline__ void mma_fp16(float d[4], uint32_t a0, uint32_t a1,
                                         uint32_t a2, uint32_t a3,
                                         uint32_t b0, uint32_t b1) {
    asm volatile(
        "mma.sync.aligned.m16n8k16.row.col.f32.f16.f16.f32 "
        "{%0,%1,%2,%3}, {%4,%5,%6,%7}, {%8,%9}, {%0,%1,%2,%3};"
        : "+f"(d[0]), "+f"(d[1]), "+f"(d[2]), "+f"(d[3])
        : "r"(a0), "r"(a1), "r"(a2), "r"(a3), "r"(b0), "r"(b1));
}
#define CP_ASYNC16(dst, src) \
    asm volatile("cp.async.ca.shared.global [%0], [%1], 16;" :: "r"(dst), "l"(src))
#define CP_COMMIT() asm volatile("cp.async.commit_group;" ::: "memory")
#define CP_WAIT0()  asm volatile("cp.async.wait_group 0;" ::: "memory")

// ---------------------------------------------------------------------------
// Transpose + fp16 convert: [B, C, HW] -> [B, HW, C] half
// ---------------------------------------------------------------------------
__global__ void transpose_x_kernel(const float* __restrict__ x) {
    __shared__ float tile[32][33];
    const int b  = blockIdx.z;
    const int sb = blockIdx.x * 32;
    const int cb = blockIdx.y * 32;
    const int tx = threadIdx.x;
    const int ty = threadIdx.y;
    const float* xb = x + (size_t)b * C_ * S_;
#pragma unroll
    for (int i = 0; i < 32; i += 8)
        tile[ty + i][tx] = xb[(size_t)(cb + ty + i) * S_ + sb + tx];
    __syncthreads();
    half* xtb = g_xth + (size_t)b * S_ * C_;
#pragma unroll
    for (int i = 0; i < 32; i += 8)
        xtb[(size_t)(sb + ty + i) * C_ + cb + tx] = __float2half(tile[tx][ty + i]);
}

// ---------------------------------------------------------------------------
// Prep weights: fp16 A images [q][co][40]
// ---------------------------------------------------------------------------
__global__ void prep_w_kernel(const float* __restrict__ w) {
    int idx = blockIdx.x * blockDim.x + threadIdx.x;
    if (idx >= NCH * CO_ * ASTRH) return;
    int cc = idx % ASTRH;
    int co = (idx / ASTRH) & 255;
    int q  = idx / (ASTRH * CO_);
    int k  = q >> 3;
    int c  = (q & 7) * 32 + cc;
    half v = __float2half(0.0f);
    if (cc < 32) v = __float2half(w[((size_t)co * C_ + c) * KT_ + k]);
    g_wAh[idx] = v;
}

// ---------------------------------------------------------------------------
// Main: fp16 mma.sync implicit GEMM with fp16 bilinear-gathered B
// ---------------------------------------------------------------------------
__global__ __launch_bounds__(NTH, 1) void deform_fp16_kernel(
    const float* __restrict__ offset, float* __restrict__ out)
{
    extern __shared__ __align__(1024) char smem[];
    const uint32_t sbase = smem_u32(smem);
    Meta* metap = (Meta*)(smem + SM_META);

    const int tid  = threadIdx.x;
    const int lane = tid & 31;
    const int warp = tid >> 5;
    const int b    = blockIdx.y;
    const int p0   = blockIdx.x * BN;

    const int g   = lane >> 2;
    const int tig = lane & 3;
    const int wm  = (warp >> 2) * 64;   // warp m origin
    const int wn  = (warp & 3) * 32;    // warp n origin

    // B build mapping: 4 threads per position, 8 channels each
    const int pl  = tid >> 2;
    const int ch0 = (tid & 3) * 8;

    const half*  xthb = g_xth + (size_t)b * S_ * C_;
    const float* offb = offset + (size_t)b * (2 * KT_) * S_;

    float acc[4][4][4];
#pragma unroll
    for (int i = 0; i < 4; ++i)
#pragma unroll
        for (int j = 0; j < 4; ++j)
#pragma unroll
            for (int r = 0; r < 4; ++r) acc[i][j][r] = 0.0f;

    const uint32_t aRowOff = (uint32_t)(wm + (lane & 7) + ((lane >> 3) & 1) * 8) * (ASTRH * 2)
                           + (lane >> 4) * 16;
    const uint32_t bRowOff = (uint32_t)(wn + (lane & 7)) * (BSTRH * 2)
                           + (lane >> 3) * 16;

    auto write_meta = [&](int k) {
        if (tid < BN) {
            const int p  = p0 + tid;
            const int ho = p >> 6;
            const int wo = p & 63;
            const float sy = offb[(size_t)(2 * k) * S_ + p]     + (float)(ho - 1 + k / 3);
            const float sx = offb[(size_t)(2 * k + 1) * S_ + p] + (float)(wo - 1 + k % 3);
            const float y0f = floorf(sy), x0f = floorf(sx);
            const float dy = sy - y0f,  dx = sx - x0f;
            const int y0 = (int)y0f, x0 = (int)x0f;
            const int y1 = y0 + 1,   x1 = x0 + 1;
            const bool vy0 = (y0 >= 0) && (y0 < H_);
            const bool vy1 = (y1 >= 0) && (y1 < H_);
            const bool vx0 = (x0 >= 0) && (x0 < W_);
            const bool vx1 = (x1 >= 0) && (x1 < W_);
            const int cy0 = min(max(y0, 0), H_ - 1), cy1 = min(max(y1, 0), H_ - 1);
            const int cx0 = min(max(x0, 0), W_ - 1), cx1 = min(max(x1, 0), W_ - 1);
            Meta mm;
            mm.w0 = (1.0f - dy) * (1.0f - dx) * ((vy0 && vx0) ? 1.0f : 0.0f);
            mm.w1 = (1.0f - dy) * dx          * ((vy0 && vx1) ? 1.0f : 0.0f);
            mm.w2 = dy * (1.0f - dx)          * ((vy1 && vx0) ? 1.0f : 0.0f);
            mm.w3 = dy * dx                   * ((vy1 && vx1) ? 1.0f : 0.0f);
            mm.i0 = (cy0 * W_ + cx0) * C_;
            mm.i1 = (cy0 * W_ + cx1) * C_;
            mm.i2 = (cy1 * W_ + cx0) * C_;
            mm.i3 = (cy1 * W_ + cx1) * C_;
            metap[tid] = mm;
        }
    };

    uint32_t cv[4];
    auto do_loads = [&](int q) {
        const int s = q & 1;
        // A image via cp.async (latency hidden behind mma)
        const char* asrc = (const char*)g_wAh + (size_t)q * ASTAGE;
        const uint32_t adst = sbase + SM_A + s * ASTAGE;
#pragma unroll
        for (int i = 0; i < 3; ++i) {
            int idx = i * NTH + tid;
            if (idx < ASTAGE / 16)
                CP_ASYNC16(adst + idx * 16, asrc + idx * 16);
        }
        CP_COMMIT();
        // fp16 corner gathers: one uint4 (8 halves) per corner
        const Meta m = metap[pl];
        const half* ba = xthb + (q & 7) * 32 + ch0;
        const uint4 u0 = *(const uint4*)(ba + m.i0);
        const uint4 u1 = *(const uint4*)(ba + m.i1);
        const uint4 u2 = *(const uint4*)(ba + m.i2);
        const uint4 u3 = *(const uint4*)(ba + m.i3);
        const half2* h0 = (const half2*)&u0;
        const half2* h1 = (const half2*)&u1;
        const half2* h2 = (const half2*)&u2;
        const half2* h3 = (const half2*)&u3;
#pragma unroll
        for (int j = 0; j < 4; ++j) {
            const float2 c0 = __half22float2(h0[j]);
            const float2 c1 = __half22float2(h1[j]);
            const float2 c2 = __half22float2(h2[j]);
            const float2 c3 = __half22float2(h3[j]);
            const float fx = m.w0 * c0.x + m.w1 * c1.x + m.w2 * c2.x + m.w3 * c3.x;
            const float fy = m.w0 * c0.y + m.w1 * c1.y + m.w2 * c2.y + m.w3 * c3.y;
            half2 h = __floats2half2_rn(fx, fy);
            cv[j] = *(uint32_t*)&h;
        }
    };

    // ---- prologue ----
    write_meta(0);
    __syncthreads();
    do_loads(0);

#pragma unroll 1
    for (int q = 0; q < NCH; ++q) {
        const int s = q & 1;

        // store B columns for chunk q
        *(uint4*)(smem + SM_B + s * BSTAGE + (uint32_t)pl * (BSTRH * 2) + ch0 * 2) =
            make_uint4(cv[0], cv[1], cv[2], cv[3]);

        CP_WAIT0();          // A image for chunk q complete
        __syncthreads();

        if (((q + 1) & 7) == 0 && q + 1 < NCH) {
            write_meta((q + 1) >> 3);
            __syncthreads();
        }

        if (q + 1 < NCH) do_loads(q + 1);   // overlaps mma below

        const uint32_t aBase = sbase + SM_A + s * ASTAGE + aRowOff;
        const uint32_t bBase = sbase + SM_B + s * BSTAGE + bRowOff;

        uint32_t bf[4][4];
#pragma unroll
        for (int nt = 0; nt < 4; ++nt)
            ldsm_x4(bf[nt][0], bf[nt][1], bf[nt][2], bf[nt][3],
                    bBase + (uint32_t)nt * 8 * (BSTRH * 2));

#pragma unroll
        for (int ks = 0; ks < 2; ++ks) {
#pragma unroll
            for (int mt = 0; mt < 4; ++mt) {
                uint32_t a0, a1, a2, a3;
                ldsm_x4(a0, a1, a2, a3,
                        aBase + (uint32_t)mt * 16 * (ASTRH * 2) + ks * 32);
#pragma unroll
                for (int nt = 0; nt < 4; ++nt)
                    mma_fp16(acc[mt][nt], a0, a1, a2, a3,
                             bf[nt][2 * ks], bf[nt][2 * ks + 1]);
            }
        }
    }

    // ---- epilogue ----
    float* ob = out + (size_t)b * CO_ * S_;
#pragma unroll
    for (int mt = 0; mt < 4; ++mt) {
#pragma unroll
        for (int nt = 0; nt < 4; ++nt) {
            const int crow = wm + mt * 16 + g;
            const int pcol = p0 + wn + nt * 8 + 2 * tig;
            *(float2*)&ob[(size_t)crow * S_ + pcol] =
                make_float2(acc[mt][nt][0], acc[mt][nt][1]);
            *(float2*)&ob[(size_t)(crow + 8) * S_ + pcol] =
                make_float2(acc[mt][nt][2], acc[mt][nt][3]);
        }
    }
}

// ---------------------------------------------------------------------------
// Launch
// ---------------------------------------------------------------------------
extern "C" void kernel_launch(void* const* d_in, const int* in_sizes, int n_in,
                              void* d_out, int out_size)
{
    (void)in_sizes; (void)n_in; (void)out_size;
    const float* x      = (const float*)d_in[0];
    const float* offset = (const float*)d_in[1];
    const float* weight = (const float*)d_in[2];
    float* out          = (float*)d_out;

    cudaFuncSetAttribute(deform_fp16_kernel,
                         cudaFuncAttributeMaxDynamicSharedMemorySize, SMEM_SZ);

    {
        dim3 grid(S_ / 32, C_ / 32, B_);
        dim3 block(32, 8);
        transpose_x_kernel<<<grid, block>>>(x);
    }
    {
        int n = NCH * CO_ * ASTRH;
        prep_w_kernel<<<(n + 255) / 256, 256>>>(weight);
    }
    {
        dim3 grid(S_ / BN, B_);
        deform_fp16_kernel<<<grid, NTH, SMEM_SZ>>>(offset, out);
    }
}

// round 7
// speedup vs baseline: 6.5660x; 1.1648x over previous
#include <cuda_runtime.h>
#include <cuda_fp16.h>
#include <cstdint>

// Problem constants
#define B_  4
#define C_  256
#define H_  64
#define W_  64
#define CO_ 256
#define S_  4096
#define KT_ 9

#define BN  128          // positions per CTA
#define CKC 64           // channels per K-chunk
#define NCH 36           // chunks = 9 taps * 4
#define NTH 512
#define ASTRH 72         // A row stride in halves (64 + 8 pad)
#define BSTRH 72

// Dynamic smem map (bytes)
#define ASTAGE  36864    // 256*72*2
#define BSTAGE  18432    // 128*72*2
#define SM_A    0        // 2 stages -> 73728
#define SM_B    73728    // 2 stages -> 36864
#define SM_META 110592   // Meta[128] = 4096
#define SMEM_SZ 114688

// Scratch
__device__ __align__(256) half g_xth[B_ * S_ * C_];        // x -> [B, HW, C] fp16
__device__ __align__(256) half g_wAh[NCH * CO_ * ASTRH];   // prepped fp16 A images

struct Meta { float w0, w1, w2, w3; int i0, i1, i2, i3; };

// ---------------------------------------------------------------------------
// Helpers
// ---------------------------------------------------------------------------
__device__ __forceinline__ uint32_t smem_u32(const void* p) {
    uint32_t a;
    asm("{ .reg .u64 t; cvta.to.shared.u64 t, %1; cvt.u32.u64 %0, t; }" : "=r"(a) : "l"(p));
    return a;
}
__device__ __forceinline__ void ldsm_x4(uint32_t& r0, uint32_t& r1, uint32_t& r2, uint32_t& r3,
                                        uint32_t addr) {
    asm volatile("ldmatrix.sync.aligned.m8n8.x4.shared.b16 {%0,%1,%2,%3}, [%4];"
                 : "=r"(r0), "=r"(r1), "=r"(r2), "=r"(r3) : "r"(addr));
}
__device__ __forceinline__ void mma_fp16(float d[4], uint32_t a0, uint32_t a1,
                                         uint32_t a2, uint32_t a3,
                                         uint32_t b0, uint32_t b1) {
    asm volatile(
        "mma.sync.aligned.m16n8k16.row.col.f32.f16.f16.f32 "
        "{%0,%1,%2,%3}, {%4,%5,%6,%7}, {%8,%9}, {%0,%1,%2,%3};"
        : "+f"(d[0]), "+f"(d[1]), "+f"(d[2]), "+f"(d[3])
        : "r"(a0), "r"(a1), "r"(a2), "r"(a3), "r"(b0), "r"(b1));
}
#define CP_ASYNC16(dst, src) \
    asm volatile("cp.async.ca.shared.global [%0], [%1], 16;" :: "r"(dst), "l"(src))
#define CP_COMMIT() asm volatile("cp.async.commit_group;" ::: "memory")
#define CP_WAIT0()  asm volatile("cp.async.wait_group 0;" ::: "memory")

// ---------------------------------------------------------------------------
// Transpose + fp16 convert: [B, C, HW] -> [B, HW, C] half
// ---------------------------------------------------------------------------
__global__ void transpose_x_kernel(const float* __restrict__ x) {
    __shared__ float tile[32][33];
    const int b  = blockIdx.z;
    const int sb = blockIdx.x * 32;
    const int cb = blockIdx.y * 32;
    const int tx = threadIdx.x;
    const int ty = threadIdx.y;
    const float* xb = x + (size_t)b * C_ * S_;
#pragma unroll
    for (int i = 0; i < 32; i += 8)
        tile[ty + i][tx] = xb[(size_t)(cb + ty + i) * S_ + sb + tx];
    __syncthreads();
    half* xtb = g_xth + (size_t)b * S_ * C_;
#pragma unroll
    for (int i = 0; i < 32; i += 8)
        xtb[(size_t)(sb + ty + i) * C_ + cb + tx] = __float2half(tile[tx][ty + i]);
}

// ---------------------------------------------------------------------------
// Prep weights: fp16 A images [q][co][72] (64 channels + 8 pad)
// ---------------------------------------------------------------------------
__global__ void prep_w_kernel(const float* __restrict__ w) {
    int idx = blockIdx.x * blockDim.x + threadIdx.x;
    if (idx >= NCH * CO_ * ASTRH) return;
    int cc = idx % ASTRH;
    int co = (idx / ASTRH) & 255;
    int q  = idx / (ASTRH * CO_);
    int k  = q >> 2;
    int c  = (q & 3) * CKC + cc;
    half v = __float2half(0.0f);
    if (cc < CKC) v = __float2half(w[((size_t)co * C_ + c) * KT_ + k]);
    g_wAh[idx] = v;
}

// ---------------------------------------------------------------------------
// Main: fp16 mma.sync implicit GEMM, CK=64, half2 bilinear combine
// ---------------------------------------------------------------------------
__global__ __launch_bounds__(NTH, 1) void deform_fp16_kernel(
    const float* __restrict__ offset, float* __restrict__ out)
{
    extern __shared__ __align__(1024) char smem[];
    const uint32_t sbase = smem_u32(smem);
    Meta* metap = (Meta*)(smem + SM_META);

    const int tid  = threadIdx.x;
    const int lane = tid & 31;
    const int warp = tid >> 5;
    const int b    = blockIdx.y;
    const int p0   = blockIdx.x * BN;

    const int g   = lane >> 2;
    const int tig = lane & 3;
    const int wm  = (warp >> 2) * 64;   // warp m origin
    const int wn  = (warp & 3) * 32;    // warp n origin

    // B build mapping: 4 threads per position, 16 channels each
    const int pl  = tid >> 2;
    const int ch0 = (tid & 3) * 16;

    const half*  xthb = g_xth + (size_t)b * S_ * C_;
    const float* offb = offset + (size_t)b * (2 * KT_) * S_;

    float acc[4][4][4];
#pragma unroll
    for (int i = 0; i < 4; ++i)
#pragma unroll
        for (int j = 0; j < 4; ++j)
#pragma unroll
            for (int r = 0; r < 4; ++r) acc[i][j][r] = 0.0f;

    const uint32_t aRowOff = (uint32_t)(wm + (lane & 7) + ((lane >> 3) & 1) * 8) * (ASTRH * 2)
                           + (lane >> 4) * 16;
    const uint32_t bRowOff = (uint32_t)(wn + (lane & 7)) * (BSTRH * 2)
                           + (lane >> 3) * 16;

    auto write_meta = [&](int k) {
        if (tid < BN) {
            const int p  = p0 + tid;
            const int ho = p >> 6;
            const int wo = p & 63;
            const float sy = offb[(size_t)(2 * k) * S_ + p]     + (float)(ho - 1 + k / 3);
            const float sx = offb[(size_t)(2 * k + 1) * S_ + p] + (float)(wo - 1 + k % 3);
            const float y0f = floorf(sy), x0f = floorf(sx);
            const float dy = sy - y0f,  dx = sx - x0f;
            const int y0 = (int)y0f, x0 = (int)x0f;
            const int y1 = y0 + 1,   x1 = x0 + 1;
            const bool vy0 = (y0 >= 0) && (y0 < H_);
            const bool vy1 = (y1 >= 0) && (y1 < H_);
            const bool vx0 = (x0 >= 0) && (x0 < W_);
            const bool vx1 = (x1 >= 0) && (x1 < W_);
            const int cy0 = min(max(y0, 0), H_ - 1), cy1 = min(max(y1, 0), H_ - 1);
            const int cx0 = min(max(x0, 0), W_ - 1), cx1 = min(max(x1, 0), W_ - 1);
            Meta mm;
            mm.w0 = (1.0f - dy) * (1.0f - dx) * ((vy0 && vx0) ? 1.0f : 0.0f);
            mm.w1 = (1.0f - dy) * dx          * ((vy0 && vx1) ? 1.0f : 0.0f);
            mm.w2 = dy * (1.0f - dx)          * ((vy1 && vx0) ? 1.0f : 0.0f);
            mm.w3 = dy * dx                   * ((vy1 && vx1) ? 1.0f : 0.0f);
            mm.i0 = (cy0 * W_ + cx0) * C_;
            mm.i1 = (cy0 * W_ + cx1) * C_;
            mm.i2 = (cy1 * W_ + cx0) * C_;
            mm.i3 = (cy1 * W_ + cx1) * C_;
            metap[tid] = mm;
        }
    };

    uint32_t cv[8];
    auto do_loads = [&](int q) {
        const int s = q & 1;
        // A image via cp.async
        const char* asrc = (const char*)g_wAh + (size_t)q * ASTAGE;
        const uint32_t adst = sbase + SM_A + s * ASTAGE;
#pragma unroll
        for (int i = 0; i < 5; ++i) {
            int idx = i * NTH + tid;
            if (idx < ASTAGE / 16)
                CP_ASYNC16(adst + idx * 16, asrc + idx * 16);
        }
        CP_COMMIT();
        // fp16 corner gathers: 2 uint4 (16 halves) per corner
        const Meta m = metap[pl];
        const half2 W0 = __float2half2_rn(m.w0);
        const half2 W1 = __float2half2_rn(m.w1);
        const half2 W2 = __float2half2_rn(m.w2);
        const half2 W3 = __float2half2_rn(m.w3);
        const half* ba = xthb + (q & 3) * CKC + ch0;
        uint4 u0[2], u1[2], u2[2], u3[2];
        u0[0] = *(const uint4*)(ba + m.i0);  u0[1] = *(const uint4*)(ba + m.i0 + 8);
        u1[0] = *(const uint4*)(ba + m.i1);  u1[1] = *(const uint4*)(ba + m.i1 + 8);
        u2[0] = *(const uint4*)(ba + m.i2);  u2[1] = *(const uint4*)(ba + m.i2 + 8);
        u3[0] = *(const uint4*)(ba + m.i3);  u3[1] = *(const uint4*)(ba + m.i3 + 8);
        const half2* h0 = (const half2*)u0;
        const half2* h1 = (const half2*)u1;
        const half2* h2 = (const half2*)u2;
        const half2* h3 = (const half2*)u3;
#pragma unroll
        for (int j = 0; j < 8; ++j) {
            half2 t0 = __hfma2(W1, h1[j], __hmul2(W0, h0[j]));
            half2 t1 = __hfma2(W3, h3[j], __hmul2(W2, h2[j]));
            half2 r  = __hadd2(t0, t1);
            cv[j] = *(uint32_t*)&r;
        }
    };

    // ---- prologue ----
    write_meta(0);
    __syncthreads();
    do_loads(0);

#pragma unroll 1
    for (int q = 0; q < NCH; ++q) {
        const int s = q & 1;

        // store B columns for chunk q (32 bytes per thread)
        {
            char* bp = smem + SM_B + s * BSTAGE + (uint32_t)pl * (BSTRH * 2) + ch0 * 2;
            *(uint4*)(bp)      = make_uint4(cv[0], cv[1], cv[2], cv[3]);
            *(uint4*)(bp + 16) = make_uint4(cv[4], cv[5], cv[6], cv[7]);
        }

        CP_WAIT0();          // A image for chunk q complete
        __syncthreads();

        if (((q + 1) & 3) == 0 && q + 1 < NCH) {
            write_meta((q + 1) >> 2);
            __syncthreads();
        }

        if (q + 1 < NCH) do_loads(q + 1);   // overlaps mma below

        const uint32_t aBase = sbase + SM_A + s * ASTAGE + aRowOff;
        const uint32_t bBase = sbase + SM_B + s * BSTAGE + bRowOff;

#pragma unroll
        for (int h = 0; h < 2; ++h) {
            uint32_t bf[4][4];
#pragma unroll
            for (int nt = 0; nt < 4; ++nt)
                ldsm_x4(bf[nt][0], bf[nt][1], bf[nt][2], bf[nt][3],
                        bBase + (uint32_t)nt * 8 * (BSTRH * 2) + h * 64);
#pragma unroll
            for (int ks = 0; ks < 2; ++ks) {
#pragma unroll
                for (int mt = 0; mt < 4; ++mt) {
                    uint32_t a0, a1, a2, a3;
                    ldsm_x4(a0, a1, a2, a3,
                            aBase + (uint32_t)mt * 16 * (ASTRH * 2) + h * 64 + ks * 32);
#pragma unroll
                    for (int nt = 0; nt < 4; ++nt)
                        mma_fp16(acc[mt][nt], a0, a1, a2, a3,
                                 bf[nt][2 * ks], bf[nt][2 * ks + 1]);
                }
            }
        }
    }

    // ---- epilogue ----
    float* ob = out + (size_t)b * CO_ * S_;
#pragma unroll
    for (int mt = 0; mt < 4; ++mt) {
#pragma unroll
        for (int nt = 0; nt < 4; ++nt) {
            const int crow = wm + mt * 16 + g;
            const int pcol = p0 + wn + nt * 8 + 2 * tig;
            *(float2*)&ob[(size_t)crow * S_ + pcol] =
                make_float2(acc[mt][nt][0], acc[mt][nt][1]);
            *(float2*)&ob[(size_t)(crow + 8) * S_ + pcol] =
                make_float2(acc[mt][nt][2], acc[mt][nt][3]);
        }
    }
}

// ---------------------------------------------------------------------------
// Launch
// ---------------------------------------------------------------------------
extern "C" void kernel_launch(void* const* d_in, const int* in_sizes, int n_in,
                              void* d_out, int out_size)
{
    (void)in_sizes; (void)n_in; (void)out_size;
    const float* x      = (const float*)d_in[0];
    const float* offset = (const float*)d_in[1];
    const float* weight = (const float*)d_in[2];
    float* out          = (float*)d_out;

    cudaFuncSetAttribute(deform_fp16_kernel,
                         cudaFuncAttributeMaxDynamicSharedMemorySize, SMEM_SZ);

    {
        dim3 grid(S_ / 32, C_ / 32, B_);
        dim3 block(32, 8);
        transpose_x_kernel<<<grid, block>>>(x);
    }
    {
        int n = NCH * CO_ * ASTRH;
        prep_w_kernel<<<(n + 255) / 256, 256>>>(weight);
    }
    {
        dim3 grid(S_ / BN, B_);
        deform_fp16_kernel<<<grid, NTH, SMEM_SZ>>>(offset, out);
    }
}